// round 1
// baseline (speedup 1.0000x reference)
#include <cuda_runtime.h>

#define NBATCH 1024
#define NV     6890
#define NJ     24
#define NBETA  10
#define NPOSE  207
#define NK     19
#define V3     20670          // NV*3
#define KTOT   218            // 207 pose_feature + 10 shape + 1 (v_template)

__constant__ int c_parents[NJ] = {0,0,0,0,1,2,3,4,5,6,7,8,9,9,9,12,13,14,16,17,18,19,20,21};

// Scratch (device globals; no allocation allowed)
__device__ float g_coef[NBATCH * KTOT];      // per-batch blend coefficients
__device__ float g_A[NBATCH * NJ * 12];      // per-batch relative transforms, 3x4 rows
__device__ float g_Mjt[NJ * 11 * 3];         // [k][nb(10) | v_template(1)][xyz]

// ---------------------------------------------------------------------------
// K0: M[k,nb,c] = sum_v reg[v,k]*shapedirs[nb, v*3+c];  Jt[k,c] = sum_v reg[v,k]*v_template[v,c]
// ---------------------------------------------------------------------------
__global__ __launch_bounds__(256) void k0_mjt(
    const float* __restrict__ reg,        // [V, 24]
    const float* __restrict__ shapedirs,  // [10, V3]
    const float* __restrict__ v_template) // [V, 3]
{
    int k = blockIdx.x;      // joint
    int col = blockIdx.y;    // 0..9 shapedirs row, 10 = v_template
    int tid = threadIdx.x;
    const float* X = (col < NBETA) ? (shapedirs + (size_t)col * V3) : v_template;
    float a0 = 0.f, a1 = 0.f, a2 = 0.f;
    for (int v = tid; v < NV; v += 256) {
        float r = reg[v * NJ + k];
        a0 += r * X[v * 3 + 0];
        a1 += r * X[v * 3 + 1];
        a2 += r * X[v * 3 + 2];
    }
    __shared__ float s_part[8][3];
    #pragma unroll
    for (int off = 16; off; off >>= 1) {
        a0 += __shfl_down_sync(0xffffffffu, a0, off);
        a1 += __shfl_down_sync(0xffffffffu, a1, off);
        a2 += __shfl_down_sync(0xffffffffu, a2, off);
    }
    int lane = tid & 31, w = tid >> 5;
    if (lane == 0) { s_part[w][0] = a0; s_part[w][1] = a1; s_part[w][2] = a2; }
    __syncthreads();
    if (tid == 0) {
        float r0 = 0.f, r1 = 0.f, r2 = 0.f;
        #pragma unroll
        for (int i = 0; i < 8; i++) { r0 += s_part[i][0]; r1 += s_part[i][1]; r2 += s_part[i][2]; }
        g_Mjt[(k * 11 + col) * 3 + 0] = r0;
        g_Mjt[(k * 11 + col) * 3 + 1] = r1;
        g_Mjt[(k * 11 + col) * 3 + 2] = r2;
    }
}

// ---------------------------------------------------------------------------
// K1: per-batch Rodrigues, coef vector, joints (via Mjt), kinematic chain, rel A
// ---------------------------------------------------------------------------
__global__ __launch_bounds__(64) void k1_batch(
    const float* __restrict__ in,     // [B, 82]
    float* __restrict__ out_Rs)       // [B, 24, 3, 3]
{
    int b = blockIdx.x, tid = threadIdx.x;
    __shared__ float s_R[NJ][9];
    __shared__ float s_Js[NJ][3];
    __shared__ float s_G[NJ][12];
    const float* pin = in + (size_t)b * 82;

    if (tid < NJ) {
        float ax = pin[tid * 3 + 0], ay = pin[tid * 3 + 1], az = pin[tid * 3 + 2];
        float ang = sqrtf(ax * ax + ay * ay + az * az + 1e-8f);
        float x = ax / ang, y = ay / ang, z = az / ang;
        float cth = cosf(ang), sth = sinf(ang), C = 1.f - cth;
        float R[9];
        R[0] = cth + C * x * x;  R[1] = C * x * y - sth * z; R[2] = C * x * z + sth * y;
        R[3] = C * x * y + sth * z; R[4] = cth + C * y * y;  R[5] = C * y * z - sth * x;
        R[6] = C * x * z - sth * y; R[7] = C * y * z + sth * x; R[8] = cth + C * z * z;
        #pragma unroll
        for (int i = 0; i < 9; i++) {
            s_R[tid][i] = R[i];
            out_Rs[(size_t)b * 216 + tid * 9 + i] = R[i];
        }
        if (tid >= 1) {
            #pragma unroll
            for (int i = 0; i < 9; i++)
                g_coef[(size_t)b * KTOT + (tid - 1) * 9 + i] =
                    R[i] - ((i == 0 || i == 4 || i == 8) ? 1.f : 0.f);
        }
        #pragma unroll
        for (int c = 0; c < 3; c++) {
            float val = g_Mjt[(tid * 11 + 10) * 3 + c];
            #pragma unroll
            for (int nb = 0; nb < NBETA; nb++)
                val += pin[72 + nb] * g_Mjt[(tid * 11 + nb) * 3 + c];
            s_Js[tid][c] = val;
        }
    } else if (tid < NJ + NBETA) {
        g_coef[(size_t)b * KTOT + NPOSE + (tid - NJ)] = pin[72 + (tid - NJ)];
    } else if (tid == NJ + NBETA) {
        g_coef[(size_t)b * KTOT + 217] = 1.f;
    }
    __syncthreads();

    if (tid == 0) {
        #pragma unroll
        for (int r = 0; r < 3; r++) {
            s_G[0][r * 4 + 0] = s_R[0][r * 3 + 0];
            s_G[0][r * 4 + 1] = s_R[0][r * 3 + 1];
            s_G[0][r * 4 + 2] = s_R[0][r * 3 + 2];
            s_G[0][r * 4 + 3] = s_Js[0][r];
        }
        for (int j = 1; j < NJ; j++) {
            int p = c_parents[j];
            float tx = s_Js[j][0] - s_Js[p][0];
            float ty = s_Js[j][1] - s_Js[p][1];
            float tz = s_Js[j][2] - s_Js[p][2];
            #pragma unroll
            for (int r = 0; r < 3; r++) {
                float g0 = s_G[p][r * 4 + 0], g1 = s_G[p][r * 4 + 1];
                float g2 = s_G[p][r * 4 + 2], gt = s_G[p][r * 4 + 3];
                s_G[j][r * 4 + 0] = g0 * s_R[j][0] + g1 * s_R[j][3] + g2 * s_R[j][6];
                s_G[j][r * 4 + 1] = g0 * s_R[j][1] + g1 * s_R[j][4] + g2 * s_R[j][7];
                s_G[j][r * 4 + 2] = g0 * s_R[j][2] + g1 * s_R[j][5] + g2 * s_R[j][8];
                s_G[j][r * 4 + 3] = g0 * tx + g1 * ty + g2 * tz + gt;
            }
        }
    }
    __syncthreads();

    if (tid < NJ) {
        int j = tid;
        #pragma unroll
        for (int r = 0; r < 3; r++) {
            float g0 = s_G[j][r * 4 + 0], g1 = s_G[j][r * 4 + 1], g2 = s_G[j][r * 4 + 2];
            float t = s_G[j][r * 4 + 3] - (g0 * s_Js[j][0] + g1 * s_Js[j][1] + g2 * s_Js[j][2]);
            size_t o = (size_t)b * 288 + j * 12 + r * 4;
            g_A[o + 0] = g0; g_A[o + 1] = g1; g_A[o + 2] = g2; g_A[o + 3] = t;
        }
    }
}

// ---------------------------------------------------------------------------
// K2: fused blendshape GEMM + LBS.  Block = 16 batches x 64 vertices.
// Thread micro-tile: 2 batches x 2 vertices x 3 comps.
// ---------------------------------------------------------------------------
#define TB 16
#define TV 64
#define KT 16
#define DSS 196   // 192 + pad

__global__ __launch_bounds__(256) void k2_lbs(
    const float* __restrict__ posedirs,   // [207, V3]
    const float* __restrict__ shapedirs,  // [10, V3]
    const float* __restrict__ v_template, // [V3]
    const float* __restrict__ lbsw,       // [V, 24]
    float* __restrict__ out_verts)        // [B, V, 3]
{
    __shared__ float s_coef[TB][KTOT];
    __shared__ float s_A[TB][NJ * 12];
    __shared__ float s_dirs[KT][DSS];

    int tid = threadIdx.x;
    int vbase = blockIdx.x * TV;
    int cbase = vbase * 3;
    int bbase = blockIdx.y * TB;

    for (int i = tid; i < TB * KTOT; i += 256)
        s_coef[i / KTOT][i % KTOT] = g_coef[(size_t)(bbase + i / KTOT) * KTOT + (i % KTOT)];
    for (int i = tid; i < TB * NJ * 12; i += 256)
        s_A[i / (NJ * 12)][i % (NJ * 12)] = g_A[(size_t)(bbase + i / (NJ * 12)) * (NJ * 12) + (i % (NJ * 12))];

    int vg = tid & 31;        // vertex pair within tile
    int bg = tid >> 5;        // batch pair within tile
    int b0 = bg * 2, b1 = b0 + 1;
    int col0 = vg * 6;

    float acc[12];
    #pragma unroll
    for (int i = 0; i < 12; i++) acc[i] = 0.f;

    __syncthreads();

#define K2_BODY(KKI)                                                     \
    {                                                                    \
        float p0 = s_coef[b0][kt0 + (KKI)];                              \
        float p1 = s_coef[b1][kt0 + (KKI)];                              \
        float d0 = s_dirs[(KKI)][col0 + 0];                              \
        float d1 = s_dirs[(KKI)][col0 + 1];                              \
        float d2 = s_dirs[(KKI)][col0 + 2];                              \
        float d3 = s_dirs[(KKI)][col0 + 3];                              \
        float d4 = s_dirs[(KKI)][col0 + 4];                              \
        float d5 = s_dirs[(KKI)][col0 + 5];                              \
        acc[0] += p0 * d0; acc[1] += p0 * d1; acc[2] += p0 * d2;         \
        acc[3] += p0 * d3; acc[4] += p0 * d4; acc[5] += p0 * d5;         \
        acc[6] += p1 * d0; acc[7] += p1 * d1; acc[8] += p1 * d2;         \
        acc[9] += p1 * d3; acc[10] += p1 * d4; acc[11] += p1 * d5;       \
    }

    for (int kt0 = 0; kt0 < KTOT; kt0 += KT) {
        int kmax = min(KT, KTOT - kt0);
        for (int i = tid; i < kmax * (TV * 3); i += 256) {
            int r = i / (TV * 3), cc = i % (TV * 3);
            int k = kt0 + r;
            int col = cbase + cc;
            float val = 0.f;
            if (col < V3) {
                if (k < NPOSE)              val = posedirs[(size_t)k * V3 + col];
                else if (k < NPOSE + NBETA) val = shapedirs[(size_t)(k - NPOSE) * V3 + col];
                else                        val = v_template[col];
            }
            s_dirs[r][cc] = val;
        }
        __syncthreads();
        if (kmax == KT) {
            #pragma unroll
            for (int kk = 0; kk < KT; kk++) K2_BODY(kk)
        } else {
            for (int kk = 0; kk < kmax; kk++) K2_BODY(kk)
        }
        __syncthreads();
    }

    // ---- LBS phase ----
    int v0 = vbase + vg * 2, v1 = v0 + 1;
    bool ok0 = v0 < NV, ok1 = v1 < NV;
    const float* lwp0 = lbsw + (size_t)(ok0 ? v0 : 0) * NJ;
    const float* lwp1 = lbsw + (size_t)(ok1 ? v1 : 0) * NJ;

    float vert[12];
    #pragma unroll
    for (int i = 0; i < 12; i++) vert[i] = 0.f;

    #pragma unroll 4
    for (int j = 0; j < NJ; j++) {
        float w0 = ok0 ? __ldg(lwp0 + j) : 0.f;
        float w1 = ok1 ? __ldg(lwp1 + j) : 0.f;
        const float* A0 = &s_A[b0][j * 12];
        const float* A1 = &s_A[b1][j * 12];
        #pragma unroll
        for (int c = 0; c < 3; c++) {
            float a_ = A0[c * 4 + 0], e_ = A0[c * 4 + 1], f_ = A0[c * 4 + 2], t_ = A0[c * 4 + 3];
            vert[c]     += w0 * (t_ + a_ * acc[0] + e_ * acc[1] + f_ * acc[2]);
            vert[3 + c] += w1 * (t_ + a_ * acc[3] + e_ * acc[4] + f_ * acc[5]);
            float a2 = A1[c * 4 + 0], e2 = A1[c * 4 + 1], f2 = A1[c * 4 + 2], t2 = A1[c * 4 + 3];
            vert[6 + c] += w0 * (t2 + a2 * acc[6] + e2 * acc[7] + f2 * acc[8]);
            vert[9 + c] += w1 * (t2 + a2 * acc[9] + e2 * acc[10] + f2 * acc[11]);
        }
    }

    if (ok0) {
        size_t o = ((size_t)(bbase + b0) * NV + v0) * 3;
        out_verts[o + 0] = vert[0]; out_verts[o + 1] = vert[1]; out_verts[o + 2] = vert[2];
        o = ((size_t)(bbase + b1) * NV + v0) * 3;
        out_verts[o + 0] = vert[6]; out_verts[o + 1] = vert[7]; out_verts[o + 2] = vert[8];
    }
    if (ok1) {
        size_t o = ((size_t)(bbase + b0) * NV + v1) * 3;
        out_verts[o + 0] = vert[3]; out_verts[o + 1] = vert[4]; out_verts[o + 2] = vert[5];
        o = ((size_t)(bbase + b1) * NV + v1) * 3;
        out_verts[o + 0] = vert[9]; out_verts[o + 1] = vert[10]; out_verts[o + 2] = vert[11];
    }
#undef K2_BODY
}

// ---------------------------------------------------------------------------
// K3: joints[b,k,c] = sum_v jr[v,k] * verts[b,v,c]   (deterministic reduction)
// ---------------------------------------------------------------------------
__global__ __launch_bounds__(256) void k3_joints(
    const float* __restrict__ jr,       // [V, 19]
    const float* __restrict__ verts,    // [B, V, 3]
    float* __restrict__ out_joints)     // [B, 19, 3]
{
    int b = blockIdx.x, tid = threadIdx.x;
    float acc[NK * 3];
    #pragma unroll
    for (int i = 0; i < NK * 3; i++) acc[i] = 0.f;
    const float* vb = verts + (size_t)b * NV * 3;
    for (int v = tid; v < NV; v += 256) {
        float x = vb[v * 3 + 0], y = vb[v * 3 + 1], z = vb[v * 3 + 2];
        const float* w = jr + (size_t)v * NK;
        #pragma unroll
        for (int k = 0; k < NK; k++) {
            float ww = w[k];
            acc[k * 3 + 0] += ww * x;
            acc[k * 3 + 1] += ww * y;
            acc[k * 3 + 2] += ww * z;
        }
    }
    __shared__ float s_part[8][NK * 3];
    int lane = tid & 31, wp = tid >> 5;
    #pragma unroll
    for (int i = 0; i < NK * 3; i++) {
        float vv = acc[i];
        #pragma unroll
        for (int off = 16; off; off >>= 1) vv += __shfl_down_sync(0xffffffffu, vv, off);
        if (lane == 0) s_part[wp][i] = vv;
    }
    __syncthreads();
    if (tid < NK * 3) {
        float s = 0.f;
        #pragma unroll
        for (int i = 0; i < 8; i++) s += s_part[i][tid];
        out_joints[(size_t)b * NK * 3 + tid] = s;
    }
}

// ---------------------------------------------------------------------------
extern "C" void kernel_launch(void* const* d_in, const int* in_sizes, int n_in,
                              void* d_out, int out_size) {
    const float* inputs    = (const float*)d_in[0];  // [B, 82]
    const float* v_tmpl    = (const float*)d_in[1];  // [V, 3]
    const float* shapedirs = (const float*)d_in[2];  // [10, V3]
    const float* jreg      = (const float*)d_in[3];  // [V, 24]
    const float* posedirs  = (const float*)d_in[4];  // [207, V3]
    const float* lbsw      = (const float*)d_in[5];  // [V, 24]
    const float* jntreg    = (const float*)d_in[6];  // [V, 19]

    float* out        = (float*)d_out;
    float* out_verts  = out;                                   // B*V*3
    float* out_joints = out + (size_t)NBATCH * NV * 3;         // B*19*3
    float* out_Rs     = out_joints + (size_t)NBATCH * NK * 3;  // B*24*9

    k0_mjt<<<dim3(NJ, 11), 256>>>(jreg, shapedirs, v_tmpl);
    k1_batch<<<NBATCH, 64>>>(inputs, out_Rs);
    k2_lbs<<<dim3((NV + TV - 1) / TV, NBATCH / TB), 256>>>(posedirs, shapedirs, v_tmpl, lbsw, out_verts);
    k3_joints<<<NBATCH, 256>>>(jntreg, out_verts, out_joints);
}

// round 3
// speedup vs baseline: 1.3733x; 1.3733x over previous
#include <cuda_runtime.h>

#define NBATCH 1024
#define NV     6890
#define NJ     24
#define NBETA  10
#define NPOSE  207
#define NK     19
#define V3     20670          // NV*3
#define KTOT   218            // 207 pose_feature + 10 shape + 1 (v_template)
#define NVP    6892           // NV padded to /4 for float4 loads

// ---- k2 tiling ----
#define TB   32               // batches per block
#define TC   192              // columns (vertex components) per block
#define TV   64               // vertices per block (TC/3)
#define KT   16               // k-tile
#define K2T  192              // threads in k2

__constant__ int c_parents[NJ] = {0,0,0,0,1,2,3,4,5,6,7,8,9,9,9,12,13,14,16,17,18,19,20,21};

// Scratch (device globals; no allocation allowed)
__device__ float g_coef[NBATCH * KTOT];      // per-batch blend coefficients
__device__ float g_A[NBATCH * NJ * 12];      // per-batch relative transforms, 3x4 rows
__device__ float g_Mjt[NJ * 11 * 3];         // [k][nb(10) | v_template(1)][xyz]
__device__ float g_jrT[NK * NVP];            // transposed, padded joint_regressor

// ---- packed fp32x2 helpers (FFMA is half-rate; FFMA2 restores full rate) ----
#define FFMA2(d, a, b) asm("fma.rn.f32x2 %0, %1, %2, %0;" : "+l"(d) : "l"(a), "l"(b))
#define PACK2(d, s)    asm("mov.b64 %0, {%1, %1};" : "=l"(d) : "f"(s))
#define UNPACK2(lo, hi, s) asm("mov.b64 {%0, %1}, %2;" : "=f"(lo), "=f"(hi) : "l"(s))

// ---------------------------------------------------------------------------
// K0: M[k,nb,c] = sum_v reg[v,k]*shapedirs[nb, v*3+c];  Jt[k,c] = sum_v reg[v,k]*v_template[v,c]
// ---------------------------------------------------------------------------
__global__ __launch_bounds__(256) void k0_mjt(
    const float* __restrict__ reg,        // [V, 24]
    const float* __restrict__ shapedirs,  // [10, V3]
    const float* __restrict__ v_template) // [V, 3]
{
    int k = blockIdx.x;      // joint
    int col = blockIdx.y;    // 0..9 shapedirs row, 10 = v_template
    int tid = threadIdx.x;
    const float* X = (col < NBETA) ? (shapedirs + (size_t)col * V3) : v_template;
    float a0 = 0.f, a1 = 0.f, a2 = 0.f;
    for (int v = tid; v < NV; v += 256) {
        float r = reg[v * NJ + k];
        a0 += r * X[v * 3 + 0];
        a1 += r * X[v * 3 + 1];
        a2 += r * X[v * 3 + 2];
    }
    __shared__ float s_part[8][3];
    #pragma unroll
    for (int off = 16; off; off >>= 1) {
        a0 += __shfl_down_sync(0xffffffffu, a0, off);
        a1 += __shfl_down_sync(0xffffffffu, a1, off);
        a2 += __shfl_down_sync(0xffffffffu, a2, off);
    }
    int lane = tid & 31, w = tid >> 5;
    if (lane == 0) { s_part[w][0] = a0; s_part[w][1] = a1; s_part[w][2] = a2; }
    __syncthreads();
    if (tid == 0) {
        float r0 = 0.f, r1 = 0.f, r2 = 0.f;
        #pragma unroll
        for (int i = 0; i < 8; i++) { r0 += s_part[i][0]; r1 += s_part[i][1]; r2 += s_part[i][2]; }
        g_Mjt[(k * 11 + col) * 3 + 0] = r0;
        g_Mjt[(k * 11 + col) * 3 + 1] = r1;
        g_Mjt[(k * 11 + col) * 3 + 2] = r2;
    }
}

// ---------------------------------------------------------------------------
// KT0: transpose joint_regressor into [NK][NVP], zero-padded
// ---------------------------------------------------------------------------
__global__ __launch_bounds__(256) void kt_trans(const float* __restrict__ jr) {
    int idx = blockIdx.x * 256 + threadIdx.x;
    if (idx < NK * NVP) {
        int k = idx / NVP, v = idx - k * NVP;
        g_jrT[idx] = (v < NV) ? jr[v * NK + k] : 0.f;
    }
}

// ---------------------------------------------------------------------------
// K1: per-batch Rodrigues, coef vector, joints (via Mjt), kinematic chain, rel A
// ---------------------------------------------------------------------------
__global__ __launch_bounds__(64) void k1_batch(
    const float* __restrict__ in,     // [B, 82]
    float* __restrict__ out_Rs)       // [B, 24, 3, 3]
{
    int b = blockIdx.x, tid = threadIdx.x;
    __shared__ float s_R[NJ][9];
    __shared__ float s_Js[NJ][3];
    __shared__ float s_G[NJ][12];
    const float* pin = in + (size_t)b * 82;

    if (tid < NJ) {
        float ax = pin[tid * 3 + 0], ay = pin[tid * 3 + 1], az = pin[tid * 3 + 2];
        float ang = sqrtf(ax * ax + ay * ay + az * az + 1e-8f);
        float x = ax / ang, y = ay / ang, z = az / ang;
        float cth = cosf(ang), sth = sinf(ang), C = 1.f - cth;
        float R[9];
        R[0] = cth + C * x * x;  R[1] = C * x * y - sth * z; R[2] = C * x * z + sth * y;
        R[3] = C * x * y + sth * z; R[4] = cth + C * y * y;  R[5] = C * y * z - sth * x;
        R[6] = C * x * z - sth * y; R[7] = C * y * z + sth * x; R[8] = cth + C * z * z;
        #pragma unroll
        for (int i = 0; i < 9; i++) {
            s_R[tid][i] = R[i];
            out_Rs[(size_t)b * 216 + tid * 9 + i] = R[i];
        }
        if (tid >= 1) {
            #pragma unroll
            for (int i = 0; i < 9; i++)
                g_coef[(size_t)b * KTOT + (tid - 1) * 9 + i] =
                    R[i] - ((i == 0 || i == 4 || i == 8) ? 1.f : 0.f);
        }
        #pragma unroll
        for (int c = 0; c < 3; c++) {
            float val = g_Mjt[(tid * 11 + 10) * 3 + c];
            #pragma unroll
            for (int nb = 0; nb < NBETA; nb++)
                val += pin[72 + nb] * g_Mjt[(tid * 11 + nb) * 3 + c];
            s_Js[tid][c] = val;
        }
    } else if (tid < NJ + NBETA) {
        g_coef[(size_t)b * KTOT + NPOSE + (tid - NJ)] = pin[72 + (tid - NJ)];
    } else if (tid == NJ + NBETA) {
        g_coef[(size_t)b * KTOT + 217] = 1.f;
    }
    __syncthreads();

    if (tid == 0) {
        #pragma unroll
        for (int r = 0; r < 3; r++) {
            s_G[0][r * 4 + 0] = s_R[0][r * 3 + 0];
            s_G[0][r * 4 + 1] = s_R[0][r * 3 + 1];
            s_G[0][r * 4 + 2] = s_R[0][r * 3 + 2];
            s_G[0][r * 4 + 3] = s_Js[0][r];
        }
        for (int j = 1; j < NJ; j++) {
            int p = c_parents[j];
            float tx = s_Js[j][0] - s_Js[p][0];
            float ty = s_Js[j][1] - s_Js[p][1];
            float tz = s_Js[j][2] - s_Js[p][2];
            #pragma unroll
            for (int r = 0; r < 3; r++) {
                float g0 = s_G[p][r * 4 + 0], g1 = s_G[p][r * 4 + 1];
                float g2 = s_G[p][r * 4 + 2], gt = s_G[p][r * 4 + 3];
                s_G[j][r * 4 + 0] = g0 * s_R[j][0] + g1 * s_R[j][3] + g2 * s_R[j][6];
                s_G[j][r * 4 + 1] = g0 * s_R[j][1] + g1 * s_R[j][4] + g2 * s_R[j][7];
                s_G[j][r * 4 + 2] = g0 * s_R[j][2] + g1 * s_R[j][5] + g2 * s_R[j][8];
                s_G[j][r * 4 + 3] = g0 * tx + g1 * ty + g2 * tz + gt;
            }
        }
    }
    __syncthreads();

    if (tid < NJ) {
        int j = tid;
        #pragma unroll
        for (int r = 0; r < 3; r++) {
            float g0 = s_G[j][r * 4 + 0], g1 = s_G[j][r * 4 + 1], g2 = s_G[j][r * 4 + 2];
            float t = s_G[j][r * 4 + 3] - (g0 * s_Js[j][0] + g1 * s_Js[j][1] + g2 * s_Js[j][2]);
            size_t o = (size_t)b * 288 + j * 12 + r * 4;
            g_A[o + 0] = g0; g_A[o + 1] = g1; g_A[o + 2] = g2; g_A[o + 3] = t;
        }
    }
}

// ---------------------------------------------------------------------------
// K2: fused blendshape GEMM + LBS, fp32x2 packed.
//   Block = 32 batches x 64 vertices (192 columns), 192 threads.
//   GEMM micro-tile: 4 batches x 8 cols (as 16 fp32x2 accumulators).
//   LBS micro-tile: 2 batches x 2 verts (24 fp32x2 accumulators, K=24).
// Dynamic smem layout (bytes):
//   [0,     37120)  s_A     [32][290]   (pad 290 for bank spread)
//   [37120, 65024)  s_coefT [218][32]   (overlaid by s_V [32][194] in LBS)
//   [65024, 77312)  s_dirs  [16][192]   (overlaid by s_WT [24][66] in LBS)
// ---------------------------------------------------------------------------
#define SMEM_K2 77312

__global__ __launch_bounds__(K2T) void k2_lbs(
    const float* __restrict__ posedirs,   // [207, V3]
    const float* __restrict__ shapedirs,  // [10, V3]
    const float* __restrict__ v_template, // [V3]
    const float* __restrict__ lbsw,       // [V, 24]
    float* __restrict__ out_verts)        // [B, V, 3]
{
    extern __shared__ char smem[];
    float* s_A     = (float*)smem;                 // [32][290]
    float* s_coefT = (float*)(smem + 37120);       // [218][32]
    float* s_dirs  = (float*)(smem + 65024);       // [16][192]
    float* s_V     = (float*)(smem + 37120);       // [32][194] overlay
    float* s_WT    = (float*)(smem + 65024);       // [24][66]  overlay

    int tid = threadIdx.x;
    int vbase = blockIdx.x * TV;
    int cbase = vbase * 3;
    int bbase = blockIdx.y * TB;

    // ---- stage coef (transposed) and A ----
    for (int i = tid; i < TB * KTOT; i += K2T) {
        int b = i / KTOT, k = i - b * KTOT;
        s_coefT[k * TB + b] = g_coef[(size_t)(bbase + b) * KTOT + k];
    }
    for (int i = tid; i < TB * 288; i += K2T) {
        int b = i / 288, j = i - b * 288;
        s_A[b * 290 + j] = g_A[(size_t)(bbase + b) * 288 + j];
    }
    __syncthreads();

    // ---- GEMM phase ----
    int bg = tid / 24, cg = tid - bg * 24;   // 8 batch-groups x 24 col-groups
    int bq = bg * 4;                          // 4 consecutive batches
    int cA = cg * 4, cB = 96 + cg * 4;        // two 4-col groups (16B LDS.128 each)

    unsigned long long acc[4][4];
    #pragma unroll
    for (int i = 0; i < 4; i++)
        #pragma unroll
        for (int p = 0; p < 4; p++) acc[i][p] = 0ull;

    for (int kt = 0; kt < KTOT; kt += KT) {
        int kmax = min(KT, KTOT - kt);
        for (int i = tid; i < kmax * (TC / 2); i += K2T) {
            int r = i / (TC / 2), c2 = i - r * (TC / 2);
            int col = cbase + c2 * 2;
            int k = kt + r;
            float2 val = make_float2(0.f, 0.f);
            if (col < V3) {
                const float* src;
                if (k < NPOSE)      src = posedirs + (size_t)k * V3;
                else if (k < 217)   src = shapedirs + (size_t)(k - NPOSE) * V3;
                else                src = v_template;
                val = *(const float2*)(src + col);
            }
            *(float2*)&s_dirs[r * TC + c2 * 2] = val;
        }
        __syncthreads();

        if (kmax == KT) {
            #pragma unroll
            for (int kk = 0; kk < KT; kk++) {
                float4 cf = *(const float4*)&s_coefT[(kt + kk) * TB + bq];
                unsigned long long P[4];
                PACK2(P[0], cf.x); PACK2(P[1], cf.y); PACK2(P[2], cf.z); PACK2(P[3], cf.w);
                ulonglong2 dA = *(const ulonglong2*)&s_dirs[kk * TC + cA];
                ulonglong2 dB = *(const ulonglong2*)&s_dirs[kk * TC + cB];
                unsigned long long D[4] = {dA.x, dA.y, dB.x, dB.y};
                #pragma unroll
                for (int bi = 0; bi < 4; bi++)
                    #pragma unroll
                    for (int p = 0; p < 4; p++)
                        FFMA2(acc[bi][p], P[bi], D[p]);
            }
        } else {
            for (int kk = 0; kk < kmax; kk++) {
                float4 cf = *(const float4*)&s_coefT[(kt + kk) * TB + bq];
                unsigned long long P[4];
                PACK2(P[0], cf.x); PACK2(P[1], cf.y); PACK2(P[2], cf.z); PACK2(P[3], cf.w);
                ulonglong2 dA = *(const ulonglong2*)&s_dirs[kk * TC + cA];
                ulonglong2 dB = *(const ulonglong2*)&s_dirs[kk * TC + cB];
                unsigned long long D[4] = {dA.x, dA.y, dB.x, dB.y};
                #pragma unroll
                for (int bi = 0; bi < 4; bi++)
                    #pragma unroll
                    for (int p = 0; p < 4; p++)
                        FFMA2(acc[bi][p], P[bi], D[p]);
            }
        }
        __syncthreads();
    }

    // ---- write v_posed tile into smem (overlay coefT) ----
    #pragma unroll
    for (int bi = 0; bi < 4; bi++) {
        int b = bq + bi;
        *(unsigned long long*)&s_V[b * 194 + cA]     = acc[bi][0];
        *(unsigned long long*)&s_V[b * 194 + cA + 2] = acc[bi][1];
        *(unsigned long long*)&s_V[b * 194 + cB]     = acc[bi][2];
        *(unsigned long long*)&s_V[b * 194 + cB + 2] = acc[bi][3];
    }
    // ---- stage transposed lbs weights (overlay dirs) ----
    for (int i = tid; i < NJ * TV; i += K2T) {
        int j = i >> 6, v = i & 63;
        int gv = vbase + v;
        s_WT[j * 66 + v] = (gv < NV) ? lbsw[(size_t)gv * NJ + j] : 0.f;
    }
    __syncthreads();

    // ---- LBS phase: tasks = 16 batch-pairs x 32 vertex-pairs = 512 ----
    for (int t = tid; t < 512; t += K2T) {
        int bgp = t >> 5, vg = t & 31;
        int b0 = bgp * 2, b1 = b0 + 1;
        int v0 = vg * 2,  v1 = v0 + 1;

        unsigned long long T00[6], T01[6], T10[6], T11[6];
        #pragma unroll
        for (int r = 0; r < 6; r++) { T00[r] = 0; T01[r] = 0; T10[r] = 0; T11[r] = 0; }

        #pragma unroll 4
        for (int j = 0; j < NJ; j++) {
            float2 w01 = *(const float2*)&s_WT[j * 66 + v0];
            unsigned long long W0, W1;
            PACK2(W0, w01.x); PACK2(W1, w01.y);
            const float* A0 = &s_A[b0 * 290 + j * 12];
            const float* A1 = &s_A[b1 * 290 + j * 12];
            #pragma unroll
            for (int r = 0; r < 6; r++) {
                unsigned long long a0 = *(const unsigned long long*)(A0 + 2 * r);
                unsigned long long a1 = *(const unsigned long long*)(A1 + 2 * r);
                FFMA2(T00[r], W0, a0);
                FFMA2(T01[r], W1, a0);
                FFMA2(T10[r], W0, a1);
                FFMA2(T11[r], W1, a1);
            }
        }

        int gv0 = vbase + v0, gv1 = vbase + v1;
        #pragma unroll
        for (int c = 0; c < 4; c++) {
            const unsigned long long* T = (c == 0) ? T00 : (c == 1) ? T01 : (c == 2) ? T10 : T11;
            int b  = (c < 2) ? b0 : b1;
            int v  = (c & 1) ? v1 : v0;
            int gv = (c & 1) ? gv1 : gv0;
            if (gv >= NV) continue;
            float x = s_V[b * 194 + 3 * v + 0];
            float y = s_V[b * 194 + 3 * v + 1];
            float z = s_V[b * 194 + 3 * v + 2];
            float a0, e0, f0, t0, a1, e1, f1, t1, a2, e2, f2, t2;
            UNPACK2(a0, e0, T[0]); UNPACK2(f0, t0, T[1]);
            UNPACK2(a1, e1, T[2]); UNPACK2(f1, t1, T[3]);
            UNPACK2(a2, e2, T[4]); UNPACK2(f2, t2, T[5]);
            size_t o = ((size_t)(bbase + b) * NV + gv) * 3;
            out_verts[o + 0] = fmaf(a0, x, fmaf(e0, y, fmaf(f0, z, t0)));
            out_verts[o + 1] = fmaf(a1, x, fmaf(e1, y, fmaf(f1, z, t1)));
            out_verts[o + 2] = fmaf(a2, x, fmaf(e2, y, fmaf(f2, z, t2)));
        }
    }
}

// ---------------------------------------------------------------------------
// K3: joints[b,k,c] = sum_v jrT[k][v] * verts[b,v,c]
// Vertex rows are only 8B-aligned for odd b (NV*3=20670 floats), so quad
// loads use float2 (six per quad), which are always 8B-aligned.
// ---------------------------------------------------------------------------
__global__ __launch_bounds__(256) void k3_joints(
    const float* __restrict__ verts,    // [B, V, 3]
    float* __restrict__ out_joints)     // [B, 19, 3]
{
    int b = blockIdx.x, tid = threadIdx.x;
    const float* vb = verts + (size_t)b * NV * 3;
    float acc[NK * 3];
    #pragma unroll
    for (int i = 0; i < NK * 3; i++) acc[i] = 0.f;

    const int NQ = (NV + 3) / 4;  // 1723; jrT zero-padded so tail quad is safe
    for (int q = tid; q < NQ; q += 256) {
        int v0 = q * 4;
        const float* p = vb + v0 * 3;
        float2 d0 = *(const float2*)(p + 0);
        float2 d1 = *(const float2*)(p + 2);
        float2 d2 = *(const float2*)(p + 4);
        float2 d3 = *(const float2*)(p + 6);
        float2 d4 = *(const float2*)(p + 8);
        float2 d5 = *(const float2*)(p + 10);
        float X0 = d0.x, Y0 = d0.y, Z0 = d1.x;
        float X1 = d1.y, Y1 = d2.x, Z1 = d2.y;
        float X2 = d3.x, Y2 = d3.y, Z2 = d4.x;
        float X3 = d4.y, Y3 = d5.x, Z3 = d5.y;
        #pragma unroll
        for (int k = 0; k < NK; k++) {
            float4 w = *(const float4*)&g_jrT[k * NVP + v0];
            acc[k * 3 + 0] += w.x * X0 + w.y * X1 + w.z * X2 + w.w * X3;
            acc[k * 3 + 1] += w.x * Y0 + w.y * Y1 + w.z * Y2 + w.w * Y3;
            acc[k * 3 + 2] += w.x * Z0 + w.y * Z1 + w.z * Z2 + w.w * Z3;
        }
    }

    __shared__ float s_part[8][NK * 3];
    int lane = tid & 31, wp = tid >> 5;
    #pragma unroll
    for (int i = 0; i < NK * 3; i++) {
        float vv = acc[i];
        #pragma unroll
        for (int off = 16; off; off >>= 1) vv += __shfl_down_sync(0xffffffffu, vv, off);
        if (lane == 0) s_part[wp][i] = vv;
    }
    __syncthreads();
    if (tid < NK * 3) {
        float s = 0.f;
        #pragma unroll
        for (int i = 0; i < 8; i++) s += s_part[i][tid];
        out_joints[(size_t)b * NK * 3 + tid] = s;
    }
}

// ---------------------------------------------------------------------------
extern "C" void kernel_launch(void* const* d_in, const int* in_sizes, int n_in,
                              void* d_out, int out_size) {
    const float* inputs    = (const float*)d_in[0];  // [B, 82]
    const float* v_tmpl    = (const float*)d_in[1];  // [V, 3]
    const float* shapedirs = (const float*)d_in[2];  // [10, V3]
    const float* jreg      = (const float*)d_in[3];  // [V, 24]
    const float* posedirs  = (const float*)d_in[4];  // [207, V3]
    const float* lbsw      = (const float*)d_in[5];  // [V, 24]
    const float* jntreg    = (const float*)d_in[6];  // [V, 19]

    float* out        = (float*)d_out;
    float* out_verts  = out;                                   // B*V*3
    float* out_joints = out + (size_t)NBATCH * NV * 3;         // B*19*3
    float* out_Rs     = out_joints + (size_t)NBATCH * NK * 3;  // B*24*9

    cudaFuncSetAttribute(k2_lbs, cudaFuncAttributeMaxDynamicSharedMemorySize, SMEM_K2);

    k0_mjt<<<dim3(NJ, 11), 256>>>(jreg, shapedirs, v_tmpl);
    kt_trans<<<(NK * NVP + 255) / 256, 256>>>(jntreg);
    k1_batch<<<NBATCH, 64>>>(inputs, out_Rs);
    k2_lbs<<<dim3((NV + TV - 1) / TV, NBATCH / TB), K2T, SMEM_K2>>>(
        posedirs, shapedirs, v_tmpl, lbsw, out_verts);
    k3_joints<<<NBATCH, 256>>>(out_verts, out_joints);
}